// round 4
// baseline (speedup 1.0000x reference)
#include <cuda_runtime.h>
#include <math.h>

#define BB 4
#define DIM 192
#define QDIM 576
#define HEADS 6
#define CC 32
#define HH 256
#define WW 256
#define HW 65536
#define NCHUNKS 64
#define CHUNK 1024   // HW / NCHUNKS

// ---------------- scratch (device globals; per-batch reuse) ------------------
__device__ float g_buf1[(size_t)QDIM * HW];        // conv1x1 out (one batch)
__device__ float g_buf2[(size_t)QDIM * HW];        // post-depthwise q|k|v; q slot -> qs
__device__ float g_spn[3 * HW];                    // l2norm'd superpixel
__device__ float g_spmean[DIM * HW];               // proj conv output (batch-invariant)
__device__ float g_gramp[(size_t)NCHUNKS * HEADS * 1024]; // per-chunk gram partials
__device__ float g_nqp[NCHUNKS * HEADS * 32];
__device__ float g_nkp[NCHUNKS * HEADS * 32];
__device__ float g_M[HEADS * 1024];                // combined attention matrix
__device__ float g_W2[DIM * DIM];                  // out_w folded through M

// ---------------- K1: qkv 1x1 conv == GEMM  Y[576,HW] = W[576,192] X[192,HW] --
__global__ __launch_bounds__(256) void k1_qkv(const float* __restrict__ X,
                                              const float* __restrict__ wq) {
    const int n0 = blockIdx.x * 128;
    const int oc0 = blockIdx.y * 128;
    float* Y = g_buf1;

    __shared__ float As[8][128];
    __shared__ float Xs[8][128];

    const int t = threadIdx.x;
    const int tm = t >> 4, tn = t & 15;

    float acc[8][8];
#pragma unroll
    for (int i = 0; i < 8; i++)
#pragma unroll
        for (int j = 0; j < 8; j++) acc[i][j] = 0.f;

    for (int k0 = 0; k0 < DIM; k0 += 8) {
        {
            int arow = oc0 + (t >> 1);
            int acol = k0 + (t & 1) * 4;
            float4 av = make_float4(0.f, 0.f, 0.f, 0.f);
            if (arow < QDIM) av = *(const float4*)(wq + arow * DIM + acol);
            As[(t & 1) * 4 + 0][t >> 1] = av.x;
            As[(t & 1) * 4 + 1][t >> 1] = av.y;
            As[(t & 1) * 4 + 2][t >> 1] = av.z;
            As[(t & 1) * 4 + 3][t >> 1] = av.w;
        }
        {
            float4 xv = *(const float4*)(X + (size_t)(k0 + (t >> 5)) * HW + n0 + (t & 31) * 4);
            *(float4*)&Xs[t >> 5][(t & 31) * 4] = xv;
        }
        __syncthreads();
#pragma unroll
        for (int kk = 0; kk < 8; kk++) {
            float a[8], bb[8];
            *(float4*)a = *(float4*)&As[kk][tm * 8];
            *(float4*)(a + 4) = *(float4*)&As[kk][tm * 8 + 4];
            *(float4*)bb = *(float4*)&Xs[kk][tn * 8];
            *(float4*)(bb + 4) = *(float4*)&Xs[kk][tn * 8 + 4];
#pragma unroll
            for (int i = 0; i < 8; i++)
#pragma unroll
                for (int j = 0; j < 8; j++) acc[i][j] += a[i] * bb[j];
        }
        __syncthreads();
    }
#pragma unroll
    for (int i = 0; i < 8; i++) {
        int oc = oc0 + tm * 8 + i;
        if (oc < QDIM) {
            float* p = Y + (size_t)oc * HW + n0 + tn * 8;
            *(float4*)p = make_float4(acc[i][0], acc[i][1], acc[i][2], acc[i][3]);
            *(float4*)(p + 4) = make_float4(acc[i][4], acc[i][5], acc[i][6], acc[i][7]);
        }
    }
}

// ---------------- K2: depthwise 3x3, SAME; 16 rows per block -----------------
__global__ __launch_bounds__(256) void k2_dw(const float* __restrict__ wd) {
    const int y0 = blockIdx.x * 16, ch = blockIdx.y;
    const float* in = g_buf1 + (size_t)ch * HW;
    float* out = g_buf2 + (size_t)ch * HW;

    __shared__ float s[18][WW + 2];
    const int x = threadIdx.x;
#pragma unroll
    for (int r = 0; r < 18; r++) {
        int yy = y0 - 1 + r;
        s[r][x + 1] = (yy >= 0 && yy < HH) ? in[yy * WW + x] : 0.f;
    }
    if (x < 18) s[x][0] = 0.f;
    else if (x < 36) s[x - 18][WW + 1] = 0.f;
    __syncthreads();

    const float* wp = wd + ch * 9;
    float w[9];
#pragma unroll
    for (int i = 0; i < 9; i++) w[i] = __ldg(wp + i);

#pragma unroll
    for (int r = 0; r < 16; r++) {
        float v = 0.f;
#pragma unroll
        for (int rr = 0; rr < 3; rr++)
#pragma unroll
            for (int dc = 0; dc < 3; dc++) v += w[rr * 3 + dc] * s[r + rr][x + dc];
        out[(y0 + r) * WW + x] = v;
    }
}

// ---------------- K3a: l2norm superpixel rows --------------------------------
__global__ __launch_bounds__(256) void k3a_spnorm(const float* __restrict__ sp) {
    const int row = blockIdx.x;  // ch*H + y, 768 rows
    const float* p = sp + row * WW;
    __shared__ float red[256];
    const int x = threadIdx.x;
    float v = p[x];
    red[x] = v * v;
    __syncthreads();
    for (int st = 128; st > 0; st >>= 1) {
        if (x < st) red[x] += red[x + st];
        __syncthreads();
    }
    float inv = 1.f / fmaxf(sqrtf(red[0]), 1e-12f);
    g_spn[row * WW + x] = v * inv;
}

// ---------------- K3b: proj conv 3->192 3x3 SAME -----------------------------
__global__ __launch_bounds__(256) void k3b_spmean(const float* __restrict__ wp) {
    const int y = blockIdx.x, oc = blockIdx.y;
    __shared__ float s[3][3][WW + 2];
    const int x = threadIdx.x;
#pragma unroll
    for (int ic = 0; ic < 3; ic++)
#pragma unroll
        for (int r = 0; r < 3; r++) {
            int yy = y - 1 + r;
            s[ic][r][x + 1] = (yy >= 0 && yy < HH) ? g_spn[ic * HW + yy * WW + x] : 0.f;
            if (x == 0) s[ic][r][0] = 0.f;
            if (x == 1) s[ic][r][WW + 1] = 0.f;
        }
    __syncthreads();
    float acc = 0.f;
    const float* w = wp + oc * 27;
#pragma unroll
    for (int ic = 0; ic < 3; ic++)
#pragma unroll
        for (int r = 0; r < 3; r++)
#pragma unroll
            for (int dc = 0; dc < 3; dc++)
                acc += __ldg(w + ic * 9 + r * 3 + dc) * s[ic][r][x + dc];
    g_spmean[oc * HW + y * WW + x] = acc;
}

// ---------------- K4: q row-l2norm (over W) * sp_mean -> qs (in place) -------
__global__ __launch_bounds__(256) void k4_qs() {
    const int y = blockIdx.x, c = blockIdx.y;
    float* q = g_buf2 + (size_t)c * HW + y * WW;
    __shared__ float red[256];
    const int x = threadIdx.x;
    float v = q[x];
    red[x] = v * v;
    __syncthreads();
    for (int st = 128; st > 0; st >>= 1) {
        if (x < st) red[x] += red[x + st];
        __syncthreads();
    }
    float inv = 1.f / fmaxf(sqrtf(red[0]), 1e-12f);
    q[x] = v * inv * g_spmean[c * HW + y * WW + x];
}

// ---------------- K5: Gram matrix S[c,d]=sum_n qs[c,n] k[d,n] + row sumsq ----
__global__ __launch_bounds__(256) void k5_gram() {
    const int chunk = blockIdx.x;
    const int hd = blockIdx.y;
    const int nbase = chunk * CHUNK;

    __shared__ float qs[128][33];
    __shared__ float ks[128][33];

    const int t = threadIdx.x;
    const int c0 = (t >> 4) * 2, d0 = (t & 15) * 2;
    const int lr = t >> 3;        // 0..31  (row)
    const int lc = (t & 7) * 4;   // col base

    float a00 = 0.f, a01 = 0.f, a10 = 0.f, a11 = 0.f, nacc = 0.f;

    const float* qbase = g_buf2 + (size_t)(hd * CC) * HW;
    const float* kbase = g_buf2 + (size_t)(DIM + hd * CC) * HW;

    for (int tile = 0; tile < CHUNK / 128; tile++) {
        const int n0 = nbase + tile * 128;
#pragma unroll
        for (int u = 0; u < 4; u++) {
            int col = lc + 32 * u;
            float4 qv = *(const float4*)(qbase + (size_t)lr * HW + n0 + col);
            qs[col + 0][lr] = qv.x; qs[col + 1][lr] = qv.y;
            qs[col + 2][lr] = qv.z; qs[col + 3][lr] = qv.w;
            float4 kv = *(const float4*)(kbase + (size_t)lr * HW + n0 + col);
            ks[col + 0][lr] = kv.x; ks[col + 1][lr] = kv.y;
            ks[col + 2][lr] = kv.z; ks[col + 3][lr] = kv.w;
        }
        __syncthreads();
#pragma unroll 4
        for (int nn = 0; nn < 128; nn++) {
            float q0 = qs[nn][c0], q1 = qs[nn][c0 + 1];
            float k0 = ks[nn][d0], k1 = ks[nn][d0 + 1];
            a00 += q0 * k0; a01 += q0 * k1;
            a10 += q1 * k0; a11 += q1 * k1;
        }
        if (t < 32) {
            for (int nn = 0; nn < 128; nn++) { float z = qs[nn][t]; nacc += z * z; }
        } else if (t < 64) {
            int d = t - 32;
            for (int nn = 0; nn < 128; nn++) { float z = ks[nn][d]; nacc += z * z; }
        }
        __syncthreads();
    }

    float* gp = g_gramp + ((size_t)chunk * HEADS + hd) * 1024;
    gp[c0 * 32 + d0] = a00;
    gp[c0 * 32 + d0 + 1] = a01;
    gp[(c0 + 1) * 32 + d0] = a10;
    gp[(c0 + 1) * 32 + d0 + 1] = a11;
    if (t < 32) g_nqp[(chunk * HEADS + hd) * 32 + t] = nacc;
    else if (t < 64) g_nkp[(chunk * HEADS + hd) * 32 + (t - 32)] = nacc;
}

// ---------------- K6: reduce partials, normalize, topk-soften, mix -> M ------
__global__ __launch_bounds__(1024) void k6_attn(const float* __restrict__ temp,
                                                const float* __restrict__ scales,
                                                const float* __restrict__ wmix) {
    const int hd = blockIdx.x;
    const int t = threadIdx.x;
    const int c = t >> 5, d = t & 31;

    float s = 0.f, nq = 0.f, nk = 0.f;
    for (int ch = 0; ch < NCHUNKS; ch++) {
        s += g_gramp[((size_t)ch * HEADS + hd) * 1024 + t];
        nq += g_nqp[(ch * HEADS + hd) * 32 + c];
        nk += g_nkp[(ch * HEADS + hd) * 32 + d];
    }
    float a = s * __ldg(temp + hd) /
              (fmaxf(sqrtf(nq), 1e-12f) * fmaxf(sqrtf(nk), 1e-12f));

    // rank within row (warp == row c, lane == d)
    int cg = 0, ce = 0;
#pragma unroll
    for (int j = 0; j < 32; j++) {
        float aj = __shfl_sync(0xffffffffu, a, j);
        cg += (aj > a);
        ce += (aj == a);
    }

    float w0 = __ldg(wmix), w1 = __ldg(wmix + 1);
    float wm = fmaxf(w0, w1);
    float e0 = expf(w0 - wm), e1 = expf(w1 - wm);
    float w0s = e0 / (e0 + e1), w1s = e1 / (e0 + e1);
    float ssum = __ldg(scales) + __ldg(scales + 1) + __ldg(scales + 2) + __ldg(scales + 3);

    float acc = w0s * ssum * fmaxf(a, 0.f);

    const int kks[4] = {16, 21, 24, 25};  // C/2, 2C/3, 3C/4, 4C/5
#pragma unroll
    for (int i = 0; i < 4; i++) {
        int kk = kks[i];
        unsigned mask = __ballot_sync(0xffffffffu, (cg < kk) && (kk <= cg + ce));
        float thr = __shfl_sync(0xffffffffu, a, __ffs(mask) - 1);
        float v = (a >= thr) ? a : a * 1e-6f;
        float mx = v;
#pragma unroll
        for (int off = 16; off > 0; off >>= 1) mx = fmaxf(mx, __shfl_xor_sync(0xffffffffu, mx, off));
        float e = expf(v - mx);
        float se = e;
#pragma unroll
        for (int off = 16; off > 0; off >>= 1) se += __shfl_xor_sync(0xffffffffu, se, off);
        acc += w1s * __ldg(scales + i) * (e / se);
    }
    g_M[hd * 1024 + c * 32 + d] = acc;
}

// ---------------- K6b: W2 = out_w (block) x M --------------------------------
__global__ __launch_bounds__(256) void k6b_w2(const float* __restrict__ ow) {
    const int idx = blockIdx.x * 256 + threadIdx.x;  // < 192*192
    const int oc = idx / DIM;
    const int j = idx % DIM;
    const int hd = j >> 5, d = j & 31;
    const float* owp = ow + oc * DIM + hd * 32;
    const float* mp = g_M + hd * 1024 + d;
    float acc = 0.f;
#pragma unroll
    for (int cix = 0; cix < 32; cix++) acc += __ldg(owp + cix) * mp[cix * 32];
    g_W2[idx] = acc;
}

// ---------------- K7: final = W2 (192x192) @ v (192xHW) ----------------------
__global__ __launch_bounds__(256) void k7_out(float* __restrict__ ob) {
    const int n0 = blockIdx.x * 64;
    const float* vbase = g_buf2 + (size_t)(2 * DIM) * HW;
    const float* w2 = g_W2;

    __shared__ float ws[16][196];
    __shared__ float vs[16][64];

    const int t = threadIdx.x;
    const int tm = t >> 4, tn = t & 15;

    float acc[48];
#pragma unroll
    for (int i = 0; i < 48; i++) acc[i] = 0.f;

    for (int j0 = 0; j0 < DIM; j0 += 16) {
#pragma unroll
        for (int u = 0; u < 12; u++) {
            int idx = t + 256 * u;  // 0..3071
            int oc = idx >> 4, jj = idx & 15;
            ws[jj][oc] = w2[oc * DIM + j0 + jj];
        }
        *(float4*)&vs[t >> 4][(t & 15) * 4] =
            *(const float4*)(vbase + (size_t)(j0 + (t >> 4)) * HW + n0 + (t & 15) * 4);
        __syncthreads();
#pragma unroll
        for (int j = 0; j < 16; j++) {
            float bbv[4];
            *(float4*)bbv = *(float4*)&vs[j][tn * 4];
            float af[12];
            *(float4*)af = *(float4*)&ws[j][tm * 12];
            *(float4*)(af + 4) = *(float4*)&ws[j][tm * 12 + 4];
            *(float4*)(af + 8) = *(float4*)&ws[j][tm * 12 + 8];
#pragma unroll
            for (int i = 0; i < 12; i++)
#pragma unroll
                for (int q = 0; q < 4; q++) acc[i * 4 + q] += af[i] * bbv[q];
        }
        __syncthreads();
    }

#pragma unroll
    for (int i = 0; i < 12; i++) {
        int oc = tm * 12 + i;
        *(float4*)(ob + (size_t)oc * HW + n0 + tn * 4) =
            make_float4(acc[i * 4], acc[i * 4 + 1], acc[i * 4 + 2], acc[i * 4 + 3]);
    }
}

// -----------------------------------------------------------------------------
extern "C" void kernel_launch(void* const* d_in, const int* in_sizes, int n_in,
                              void* d_out, int out_size) {
    const float* x      = (const float*)d_in[0];
    const float* sp     = (const float*)d_in[1];
    const float* qkv_w  = (const float*)d_in[2];
    const float* dw_w   = (const float*)d_in[3];
    const float* proj_w = (const float*)d_in[4];
    const float* out_w  = (const float*)d_in[5];
    const float* temp   = (const float*)d_in[6];
    const float* scales = (const float*)d_in[7];
    const float* wmix   = (const float*)d_in[8];
    float* out = (float*)d_out;

    // batch-invariant superpixel path
    k3a_spnorm<<<768, 256>>>(sp);
    k3b_spmean<<<dim3(256, 192), 256>>>(proj_w);

    for (int b = 0; b < BB; b++) {
        const float* xb = x + (size_t)b * DIM * HW;
        float* ob = out + (size_t)b * DIM * HW;
        k1_qkv<<<dim3(512, 5), 256>>>(xb, qkv_w);
        k2_dw<<<dim3(16, 576), 256>>>(dw_w);
        k4_qs<<<dim3(256, 192), 256>>>();
        k5_gram<<<dim3(NCHUNKS, HEADS), 256>>>();
        k6_attn<<<HEADS, 1024>>>(temp, scales, wmix);
        k6b_w2<<<144, 256>>>(out_w);
        k7_out<<<1024, 256>>>(ob);
    }
}

// round 6
// speedup vs baseline: 1.1934x; 1.1934x over previous
#include <cuda_runtime.h>
#include <math.h>

#define BB 4
#define DIM 192
#define QDIM 576
#define HEADS 6
#define CC 32
#define HH 256
#define WW 256
#define HW 65536
#define KK 192
#define NCHUNKS 64
#define CHUNK 1024   // HW / NCHUNKS

// ---------------- scratch (device globals; per-batch reuse) ------------------
__device__ float g_buf1[(size_t)QDIM * HW];        // conv1x1 out (one batch)
__device__ float g_buf2[(size_t)QDIM * HW];        // post-depthwise q|k|v; q slot -> qs
__device__ float g_spn[3 * HW];                    // l2norm'd superpixel
__device__ float g_spmean[DIM * HW];               // proj conv output (batch-invariant)
__device__ float g_gramp[(size_t)NCHUNKS * HEADS * 1024]; // per-chunk gram partials
__device__ float g_nqp[NCHUNKS * HEADS * 32];
__device__ float g_nkp[NCHUNKS * HEADS * 32];
__device__ float g_M[HEADS * 1024];                // combined attention matrix
__device__ float g_W2[DIM * DIM];                  // out_w folded through M

// ---------------- tf32 helpers ----------------------------------------------
__device__ __forceinline__ unsigned f2tf32(float v) {
    unsigned r;
    asm("cvt.rna.tf32.f32 %0, %1;" : "=r"(r) : "f"(v));
    return r;
}

__device__ __forceinline__ void mma_tf32(float c[4], const unsigned a[4],
                                         const unsigned b[2]) {
    asm volatile(
        "mma.sync.aligned.m16n8k8.row.col.f32.tf32.tf32.f32 "
        "{%0,%1,%2,%3}, {%4,%5,%6,%7}, {%8,%9}, {%0,%1,%2,%3};\n"
        : "+f"(c[0]), "+f"(c[1]), "+f"(c[2]), "+f"(c[3])
        : "r"(a[0]), "r"(a[1]), "r"(a[2]), "r"(a[3]), "r"(b[0]), "r"(b[1]));
}

// ---------------- GEMM: Y[M,HW] = A[M,192] @ X[192,HW], 3xTF32 split --------
// Block 128x128, 8 warps of 64x32. A row-major [M,192], X row-major [192,HW].
// Ap==null -> g_W2 ; Xp==null -> v slot of g_buf2 ; Yp==null -> g_buf1.
template <int M>
__global__ __launch_bounds__(256) void gemm_tf32(const float* __restrict__ Ap,
                                                 const float* __restrict__ Xp,
                                                 float* __restrict__ Yp) {
    const float* A = Ap ? Ap : g_W2;
    const float* X = Xp ? Xp : (g_buf2 + (size_t)(2 * DIM) * HW);
    float* Y = Yp ? Yp : g_buf1;

    const int t = threadIdx.x;
    const int lane = t & 31, w = t >> 5;
    const int wm = w >> 2, wn = w & 3;            // warp grid 2 x 4
    const int g = lane >> 2, tig = lane & 3;
    const int bm = blockIdx.y * 128, bn = blockIdx.x * 128;

    __shared__ float As[16][136];   // [k][m], stride 136 => bank-bijective frags
    __shared__ float Xs[16][136];   // [k][n]

    float c[4][4][4];
#pragma unroll
    for (int mi = 0; mi < 4; mi++)
#pragma unroll
        for (int ni = 0; ni < 4; ni++)
#pragma unroll
            for (int r = 0; r < 4; r++) c[mi][ni][r] = 0.f;

    for (int k0 = 0; k0 < KK; k0 += 16) {
        // load A tile: 128 m x 16 k  (transposed scatter into As[k][m])
#pragma unroll
        for (int i = 0; i < 2; i++) {
            int fid = t + i * 256;        // 0..511
            int m = fid >> 2, kq = fid & 3;
            float4 av = make_float4(0.f, 0.f, 0.f, 0.f);
            if (bm + m < M)
                av = *(const float4*)(A + (size_t)(bm + m) * KK + k0 + kq * 4);
            As[kq * 4 + 0][m] = av.x;
            As[kq * 4 + 1][m] = av.y;
            As[kq * 4 + 2][m] = av.z;
            As[kq * 4 + 3][m] = av.w;
        }
        // load X tile: 16 k x 128 n
#pragma unroll
        for (int i = 0; i < 2; i++) {
            int fid = t + i * 256;
            int k = fid >> 5, n4 = (fid & 31) * 4;
            *(float4*)&Xs[k][n4] =
                *(const float4*)(X + (size_t)(k0 + k) * HW + bn + n4);
        }
        __syncthreads();

#pragma unroll
        for (int kh = 0; kh < 2; kh++) {
            const int kb = kh * 8;
            unsigned ahi[4][4], alo[4][4], bhi[4][2], blo[4][2];
#pragma unroll
            for (int mi = 0; mi < 4; mi++) {
                int mb = wm * 64 + mi * 16 + g;
                float v0 = As[kb + tig][mb];
                float v1 = As[kb + tig][mb + 8];
                float v2 = As[kb + tig + 4][mb];
                float v3 = As[kb + tig + 4][mb + 8];
                ahi[mi][0] = f2tf32(v0);
                alo[mi][0] = f2tf32(v0 - __uint_as_float(ahi[mi][0]));
                ahi[mi][1] = f2tf32(v1);
                alo[mi][1] = f2tf32(v1 - __uint_as_float(ahi[mi][1]));
                ahi[mi][2] = f2tf32(v2);
                alo[mi][2] = f2tf32(v2 - __uint_as_float(ahi[mi][2]));
                ahi[mi][3] = f2tf32(v3);
                alo[mi][3] = f2tf32(v3 - __uint_as_float(ahi[mi][3]));
            }
#pragma unroll
            for (int ni = 0; ni < 4; ni++) {
                int nb = wn * 32 + ni * 8 + g;
                float u0 = Xs[kb + tig][nb];
                float u1 = Xs[kb + tig + 4][nb];
                bhi[ni][0] = f2tf32(u0);
                blo[ni][0] = f2tf32(u0 - __uint_as_float(bhi[ni][0]));
                bhi[ni][1] = f2tf32(u1);
                blo[ni][1] = f2tf32(u1 - __uint_as_float(bhi[ni][1]));
            }
#pragma unroll
            for (int mi = 0; mi < 4; mi++)
#pragma unroll
                for (int ni = 0; ni < 4; ni++) {
                    mma_tf32(c[mi][ni], ahi[mi], bhi[ni]);
                    mma_tf32(c[mi][ni], ahi[mi], blo[ni]);
                    mma_tf32(c[mi][ni], alo[mi], bhi[ni]);
                }
        }
        __syncthreads();
    }

    // epilogue: c0=(g,2tig) c1=(g,2tig+1) c2=(g+8,2tig) c3=(g+8,2tig+1)
#pragma unroll
    for (int mi = 0; mi < 4; mi++) {
        int m0 = bm + wm * 64 + mi * 16 + g;
#pragma unroll
        for (int ni = 0; ni < 4; ni++) {
            int n = bn + wn * 32 + ni * 8 + 2 * tig;
            if (m0 < M)
                *(float2*)(Y + (size_t)m0 * HW + n) =
                    make_float2(c[mi][ni][0], c[mi][ni][1]);
            if (m0 + 8 < M)
                *(float2*)(Y + (size_t)(m0 + 8) * HW + n) =
                    make_float2(c[mi][ni][2], c[mi][ni][3]);
        }
    }
}

// ---------------- K2: depthwise 3x3, SAME; 16 rows per block -----------------
__global__ __launch_bounds__(256) void k2_dw(const float* __restrict__ wd) {
    const int y0 = blockIdx.x * 16, ch = blockIdx.y;
    const float* in = g_buf1 + (size_t)ch * HW;
    float* out = g_buf2 + (size_t)ch * HW;

    __shared__ float s[18][WW + 2];
    const int x = threadIdx.x;
#pragma unroll
    for (int r = 0; r < 18; r++) {
        int yy = y0 - 1 + r;
        s[r][x + 1] = (yy >= 0 && yy < HH) ? in[yy * WW + x] : 0.f;
    }
    if (x < 18) s[x][0] = 0.f;
    else if (x < 36) s[x - 18][WW + 1] = 0.f;
    __syncthreads();

    const float* wp = wd + ch * 9;
    float w[9];
#pragma unroll
    for (int i = 0; i < 9; i++) w[i] = __ldg(wp + i);

#pragma unroll
    for (int r = 0; r < 16; r++) {
        float v = 0.f;
#pragma unroll
        for (int rr = 0; rr < 3; rr++)
#pragma unroll
            for (int dc = 0; dc < 3; dc++) v += w[rr * 3 + dc] * s[r + rr][x + dc];
        out[(y0 + r) * WW + x] = v;
    }
}

// ---------------- K3a: l2norm superpixel rows --------------------------------
__global__ __launch_bounds__(256) void k3a_spnorm(const float* __restrict__ sp) {
    const int row = blockIdx.x;  // ch*H + y, 768 rows
    const float* p = sp + row * WW;
    __shared__ float red[256];
    const int x = threadIdx.x;
    float v = p[x];
    red[x] = v * v;
    __syncthreads();
    for (int st = 128; st > 0; st >>= 1) {
        if (x < st) red[x] += red[x + st];
        __syncthreads();
    }
    float inv = 1.f / fmaxf(sqrtf(red[0]), 1e-12f);
    g_spn[row * WW + x] = v * inv;
}

// ---------------- K3b: proj conv 3->192 3x3 SAME -----------------------------
__global__ __launch_bounds__(256) void k3b_spmean(const float* __restrict__ wp) {
    const int y = blockIdx.x, oc = blockIdx.y;
    __shared__ float s[3][3][WW + 2];
    const int x = threadIdx.x;
#pragma unroll
    for (int ic = 0; ic < 3; ic++)
#pragma unroll
        for (int r = 0; r < 3; r++) {
            int yy = y - 1 + r;
            s[ic][r][x + 1] = (yy >= 0 && yy < HH) ? g_spn[ic * HW + yy * WW + x] : 0.f;
            if (x == 0) s[ic][r][0] = 0.f;
            if (x == 1) s[ic][r][WW + 1] = 0.f;
        }
    __syncthreads();
    float acc = 0.f;
    const float* w = wp + oc * 27;
#pragma unroll
    for (int ic = 0; ic < 3; ic++)
#pragma unroll
        for (int r = 0; r < 3; r++)
#pragma unroll
            for (int dc = 0; dc < 3; dc++)
                acc += __ldg(w + ic * 9 + r * 3 + dc) * s[ic][r][x + dc];
    g_spmean[oc * HW + y * WW + x] = acc;
}

// ---------------- K4: q row-l2norm (over W) * sp_mean -> qs (in place) -------
__global__ __launch_bounds__(256) void k4_qs() {
    const int y = blockIdx.x, c = blockIdx.y;
    float* q = g_buf2 + (size_t)c * HW + y * WW;
    __shared__ float red[256];
    const int x = threadIdx.x;
    float v = q[x];
    red[x] = v * v;
    __syncthreads();
    for (int st = 128; st > 0; st >>= 1) {
        if (x < st) red[x] += red[x + st];
        __syncthreads();
    }
    float inv = 1.f / fmaxf(sqrtf(red[0]), 1e-12f);
    q[x] = v * inv * g_spmean[c * HW + y * WW + x];
}

// ---------------- K5: Gram matrix S[c,d]=sum_n qs[c,n] k[d,n] + row sumsq ----
__global__ __launch_bounds__(256) void k5_gram() {
    const int chunk = blockIdx.x;
    const int hd = blockIdx.y;
    const int nbase = chunk * CHUNK;

    __shared__ float qs[128][33];
    __shared__ float ks[128][33];

    const int t = threadIdx.x;
    const int c0 = (t >> 4) * 2, d0 = (t & 15) * 2;
    const int lr = t >> 3;        // 0..31  (row)
    const int lc = (t & 7) * 4;   // col base

    float a00 = 0.f, a01 = 0.f, a10 = 0.f, a11 = 0.f, nacc = 0.f;

    const float* qbase = g_buf2 + (size_t)(hd * CC) * HW;
    const float* kbase = g_buf2 + (size_t)(DIM + hd * CC) * HW;

    for (int tile = 0; tile < CHUNK / 128; tile++) {
        const int n0 = nbase + tile * 128;
#pragma unroll
        for (int u = 0; u < 4; u++) {
            int col = lc + 32 * u;
            float4 qv = *(const float4*)(qbase + (size_t)lr * HW + n0 + col);
            qs[col + 0][lr] = qv.x; qs[col + 1][lr] = qv.y;
            qs[col + 2][lr] = qv.z; qs[col + 3][lr] = qv.w;
            float4 kv = *(const float4*)(kbase + (size_t)lr * HW + n0 + col);
            ks[col + 0][lr] = kv.x; ks[col + 1][lr] = kv.y;
            ks[col + 2][lr] = kv.z; ks[col + 3][lr] = kv.w;
        }
        __syncthreads();
#pragma unroll 4
        for (int nn = 0; nn < 128; nn++) {
            float q0 = qs[nn][c0], q1 = qs[nn][c0 + 1];
            float k0 = ks[nn][d0], k1 = ks[nn][d0 + 1];
            a00 += q0 * k0; a01 += q0 * k1;
            a10 += q1 * k0; a11 += q1 * k1;
        }
        if (t < 32) {
            for (int nn = 0; nn < 128; nn++) { float z = qs[nn][t]; nacc += z * z; }
        } else if (t < 64) {
            int d = t - 32;
            for (int nn = 0; nn < 128; nn++) { float z = ks[nn][d]; nacc += z * z; }
        }
        __syncthreads();
    }

    float* gp = g_gramp + ((size_t)chunk * HEADS + hd) * 1024;
    gp[c0 * 32 + d0] = a00;
    gp[c0 * 32 + d0 + 1] = a01;
    gp[(c0 + 1) * 32 + d0] = a10;
    gp[(c0 + 1) * 32 + d0 + 1] = a11;
    if (t < 32) g_nqp[(chunk * HEADS + hd) * 32 + t] = nacc;
    else if (t < 64) g_nkp[(chunk * HEADS + hd) * 32 + (t - 32)] = nacc;
}

// ---------------- K6: reduce partials, normalize, topk-soften, mix -> M ------
__global__ __launch_bounds__(1024) void k6_attn(const float* __restrict__ temp,
                                                const float* __restrict__ scales,
                                                const float* __restrict__ wmix) {
    const int hd = blockIdx.x;
    const int t = threadIdx.x;
    const int c = t >> 5, d = t & 31;

    float s = 0.f, nq = 0.f, nk = 0.f;
    for (int ch = 0; ch < NCHUNKS; ch++) {
        s += g_gramp[((size_t)ch * HEADS + hd) * 1024 + t];
        nq += g_nqp[(ch * HEADS + hd) * 32 + c];
        nk += g_nkp[(ch * HEADS + hd) * 32 + d];
    }
    float a = s * __ldg(temp + hd) /
              (fmaxf(sqrtf(nq), 1e-12f) * fmaxf(sqrtf(nk), 1e-12f));

    // rank within row (warp == row c, lane == d)
    int cg = 0, ce = 0;
#pragma unroll
    for (int j = 0; j < 32; j++) {
        float aj = __shfl_sync(0xffffffffu, a, j);
        cg += (aj > a);
        ce += (aj == a);
    }

    float w0 = __ldg(wmix), w1 = __ldg(wmix + 1);
    float wm = fmaxf(w0, w1);
    float e0 = expf(w0 - wm), e1 = expf(w1 - wm);
    float w0s = e0 / (e0 + e1), w1s = e1 / (e0 + e1);
    float ssum = __ldg(scales) + __ldg(scales + 1) + __ldg(scales + 2) + __ldg(scales + 3);

    float acc = w0s * ssum * fmaxf(a, 0.f);

    const int kks[4] = {16, 21, 24, 25};  // C/2, 2C/3, 3C/4, 4C/5
#pragma unroll
    for (int i = 0; i < 4; i++) {
        int kk = kks[i];
        unsigned mask = __ballot_sync(0xffffffffu, (cg < kk) && (kk <= cg + ce));
        float thr = __shfl_sync(0xffffffffu, a, __ffs(mask) - 1);
        float v = (a >= thr) ? a : a * 1e-6f;
        float mx = v;
#pragma unroll
        for (int off = 16; off > 0; off >>= 1) mx = fmaxf(mx, __shfl_xor_sync(0xffffffffu, mx, off));
        float e = expf(v - mx);
        float se = e;
#pragma unroll
        for (int off = 16; off > 0; off >>= 1) se += __shfl_xor_sync(0xffffffffu, se, off);
        acc += w1s * __ldg(scales + i) * (e / se);
    }
    g_M[hd * 1024 + c * 32 + d] = acc;
}

// ---------------- K6b: W2 = out_w (block) x M --------------------------------
__global__ __launch_bounds__(256) void k6b_w2(const float* __restrict__ ow) {
    const int idx = blockIdx.x * 256 + threadIdx.x;  // < 192*192
    const int oc = idx / DIM;
    const int j = idx % DIM;
    const int hd = j >> 5, d = j & 31;
    const float* owp = ow + oc * DIM + hd * 32;
    const float* mp = g_M + hd * 1024 + d;
    float acc = 0.f;
#pragma unroll
    for (int cix = 0; cix < 32; cix++) acc += __ldg(owp + cix) * mp[cix * 32];
    g_W2[idx] = acc;
}

// -----------------------------------------------------------------------------
extern "C" void kernel_launch(void* const* d_in, const int* in_sizes, int n_in,
                              void* d_out, int out_size) {
    const float* x      = (const float*)d_in[0];
    const float* sp     = (const float*)d_in[1];
    const float* qkv_w  = (const float*)d_in[2];
    const float* dw_w   = (const float*)d_in[3];
    const float* proj_w = (const float*)d_in[4];
    const float* out_w  = (const float*)d_in[5];
    const float* temp   = (const float*)d_in[6];
    const float* scales = (const float*)d_in[7];
    const float* wmix   = (const float*)d_in[8];
    float* out = (float*)d_out;

    // batch-invariant superpixel path
    k3a_spnorm<<<768, 256>>>(sp);
    k3b_spmean<<<dim3(256, 192), 256>>>(proj_w);

    for (int b = 0; b < BB; b++) {
        const float* xb = x + (size_t)b * DIM * HW;
        float* ob = out + (size_t)b * DIM * HW;
        gemm_tf32<QDIM><<<dim3(512, 5), 256>>>(qkv_w, xb, nullptr);   // K1
        k2_dw<<<dim3(16, 576), 256>>>(dw_w);
        k4_qs<<<dim3(256, 192), 256>>>();
        k5_gram<<<dim3(NCHUNKS, HEADS), 256>>>();
        k6_attn<<<HEADS, 1024>>>(temp, scales, wmix);
        k6b_w2<<<144, 256>>>(out_w);
        gemm_tf32<DIM><<<dim3(512, 2), 256>>>(nullptr, nullptr, ob);  // K7
    }
}

// round 8
// speedup vs baseline: 1.5090x; 1.2644x over previous
#include <cuda_runtime.h>
#include <cuda_bf16.h>
#include <math.h>

#define BB 4
#define DIM 192
#define QDIM 576
#define HEADS 6
#define CC 32
#define HH 256
#define WW 256
#define HW 65536
#define KK 192
#define NCHUNKS 64
#define CHUNK 1024   // HW / NCHUNKS

// ---------------- scratch (device globals; per-batch reuse) ------------------
__device__ float g_buf1[(size_t)QDIM * HW];        // conv1x1 out (one batch)
__device__ float g_buf2[(size_t)QDIM * HW];        // post-depthwise q|k|v; q slot -> qs
__device__ float g_spn[3 * HW];
__device__ float g_spmean[DIM * HW];
__device__ float g_gramp[(size_t)NCHUNKS * HEADS * 1024];
__device__ float g_nqp[NCHUNKS * HEADS * 32];
__device__ float g_nkp[NCHUNKS * HEADS * 32];
__device__ float g_M[HEADS * 1024];
__device__ float g_W2[DIM * DIM];

// ---------------- bf16 helpers ------------------------------------------------
__device__ __forceinline__ unsigned short bfbits(__nv_bfloat16 h) {
    return *reinterpret_cast<unsigned short*>(&h);
}
// pack two floats into bf16x2 hi word + residual lo word
__device__ __forceinline__ void bfsplit2(float a, float b, unsigned& hi, unsigned& lo) {
    __nv_bfloat16 ha = __float2bfloat16(a), hb = __float2bfloat16(b);
    hi = (unsigned)bfbits(ha) | ((unsigned)bfbits(hb) << 16);
    __nv_bfloat16 la = __float2bfloat16(a - __bfloat162float(ha));
    __nv_bfloat16 lb = __float2bfloat16(b - __bfloat162float(hb));
    lo = (unsigned)bfbits(la) | ((unsigned)bfbits(lb) << 16);
}

__device__ __forceinline__ void mma_bf16(float c[4], const unsigned a[4],
                                         const unsigned b[2]) {
    asm volatile(
        "mma.sync.aligned.m16n8k16.row.col.f32.bf16.bf16.f32 "
        "{%0,%1,%2,%3}, {%4,%5,%6,%7}, {%8,%9}, {%0,%1,%2,%3};\n"
        : "+f"(c[0]), "+f"(c[1]), "+f"(c[2]), "+f"(c[3])
        : "r"(a[0]), "r"(a[1]), "r"(a[2]), "r"(a[3]), "r"(b[0]), "r"(b[1]));
}

// ---------------- GEMM: Y[M,HW] = A[M,192] @ X[192,HW], 3x bf16 split --------
// Block 128x128, 8 warps of 64x32. Convert-at-load: smem holds packed bf16x2
// k-pair words (hi & lo) so the inner loop is pure LDS + MMA.
// Ap==null -> g_W2 ; Xp==null -> v slot of g_buf2 ; Yp==null -> g_buf1.
template <int M>
__global__ __launch_bounds__(256) void gemm_bf16(const float* __restrict__ Ap,
                                                 const float* __restrict__ Xp,
                                                 float* __restrict__ Yp) {
    const float* A = Ap ? Ap : g_W2;
    const float* X = Xp ? Xp : (g_buf2 + (size_t)(2 * DIM) * HW);
    float* Y = Yp ? Yp : g_buf1;

    const int t = threadIdx.x;
    const int lane = t & 31, w = t >> 5;
    const int wm = w >> 2, wn = w & 3;            // warp grid 2 x 4
    const int g = lane >> 2, tig = lane & 3;
    const int bm = blockIdx.y * 128, bn = blockIdx.x * 128;

    // packed k-pair words: [kp][m or n], stride 136 -> bank-bijective frag reads
    __shared__ unsigned Ah[8][136], Al[8][136];
    __shared__ unsigned Xh[8][136], Xl[8][136];

    float c[4][4][4];
#pragma unroll
    for (int mi = 0; mi < 4; mi++)
#pragma unroll
        for (int ni = 0; ni < 4; ni++)
#pragma unroll
            for (int r = 0; r < 4; r++) c[mi][ni][r] = 0.f;

    for (int k0 = 0; k0 < KK; k0 += 16) {
        // ---- stage A tile: 128 m x 8 kp (convert fp32 -> bf16 hi/lo pairs) ----
#pragma unroll
        for (int i = 0; i < 4; i++) {
            int fid = t + i * 256;          // 0..1023
            int kp = fid & 7, m = fid >> 3;
            float2 av = make_float2(0.f, 0.f);
            if (bm + m < M)
                av = *(const float2*)(A + (size_t)(bm + m) * KK + k0 + kp * 2);
            unsigned hi, lo;
            bfsplit2(av.x, av.y, hi, lo);
            Ah[kp][m] = hi;
            Al[kp][m] = lo;
        }
        // ---- stage X tile: 8 kp x 128 n ----
        {
            int kp = t >> 5, n4 = (t & 31) * 4;
            const float* r0p = X + (size_t)(k0 + 2 * kp) * HW + bn + n4;
            float4 r0 = *(const float4*)(r0p);
            float4 r1 = *(const float4*)(r0p + HW);
            unsigned hi, lo;
            bfsplit2(r0.x, r1.x, hi, lo); Xh[kp][n4 + 0] = hi; Xl[kp][n4 + 0] = lo;
            bfsplit2(r0.y, r1.y, hi, lo); Xh[kp][n4 + 1] = hi; Xl[kp][n4 + 1] = lo;
            bfsplit2(r0.z, r1.z, hi, lo); Xh[kp][n4 + 2] = hi; Xl[kp][n4 + 2] = lo;
            bfsplit2(r0.w, r1.w, hi, lo); Xh[kp][n4 + 3] = hi; Xl[kp][n4 + 3] = lo;
        }
        __syncthreads();

        // ---- B fragments (X side), all ni at once ----
        unsigned bh[4][2], bl[4][2];
#pragma unroll
        for (int ni = 0; ni < 4; ni++) {
            int nb = wn * 32 + ni * 8 + g;
            bh[ni][0] = Xh[tig][nb];
            bh[ni][1] = Xh[tig + 4][nb];
            bl[ni][0] = Xl[tig][nb];
            bl[ni][1] = Xl[tig + 4][nb];
        }
#pragma unroll
        for (int mi = 0; mi < 4; mi++) {
            int mb = wm * 64 + mi * 16 + g;
            unsigned ah[4], al[4];
            ah[0] = Ah[tig][mb];     ah[1] = Ah[tig][mb + 8];
            ah[2] = Ah[tig + 4][mb]; ah[3] = Ah[tig + 4][mb + 8];
            al[0] = Al[tig][mb];     al[1] = Al[tig][mb + 8];
            al[2] = Al[tig + 4][mb]; al[3] = Al[tig + 4][mb + 8];
#pragma unroll
            for (int ni = 0; ni < 4; ni++) {
                mma_bf16(c[mi][ni], ah, bh[ni]);
                mma_bf16(c[mi][ni], ah, bl[ni]);
                mma_bf16(c[mi][ni], al, bh[ni]);
            }
        }
        __syncthreads();
    }

    // epilogue: c0=(g,2tig) c1=(g,2tig+1) c2=(g+8,2tig) c3=(g+8,2tig+1)
#pragma unroll
    for (int mi = 0; mi < 4; mi++) {
        int m0 = bm + wm * 64 + mi * 16 + g;
#pragma unroll
        for (int ni = 0; ni < 4; ni++) {
            int n = bn + wn * 32 + ni * 8 + 2 * tig;
            if (m0 < M)
                *(float2*)(Y + (size_t)m0 * HW + n) =
                    make_float2(c[mi][ni][0], c[mi][ni][1]);
            if (m0 + 8 < M)
                *(float2*)(Y + (size_t)(m0 + 8) * HW + n) =
                    make_float2(c[mi][ni][2], c[mi][ni][3]);
        }
    }
}

// ---------------- K2: depthwise 3x3, SAME; 16 rows per block -----------------
__global__ __launch_bounds__(256) void k2_dw(const float* __restrict__ wd) {
    const int y0 = blockIdx.x * 16, ch = blockIdx.y;
    const float* in = g_buf1 + (size_t)ch * HW;
    float* out = g_buf2 + (size_t)ch * HW;

    __shared__ float s[18][WW + 2];
    const int x = threadIdx.x;
#pragma unroll
    for (int r = 0; r < 18; r++) {
        int yy = y0 - 1 + r;
        s[r][x + 1] = (yy >= 0 && yy < HH) ? in[yy * WW + x] : 0.f;
    }
    if (x < 18) s[x][0] = 0.f;
    else if (x < 36) s[x - 18][WW + 1] = 0.f;
    __syncthreads();

    const float* wp = wd + ch * 9;
    float w[9];
#pragma unroll
    for (int i = 0; i < 9; i++) w[i] = __ldg(wp + i);

#pragma unroll
    for (int r = 0; r < 16; r++) {
        float v = 0.f;
#pragma unroll
        for (int rr = 0; rr < 3; rr++)
#pragma unroll
            for (int dc = 0; dc < 3; dc++) v += w[rr * 3 + dc] * s[r + rr][x + dc];
        out[(y0 + r) * WW + x] = v;
    }
}

// ---------------- K3a: l2norm superpixel rows --------------------------------
__global__ __launch_bounds__(256) void k3a_spnorm(const float* __restrict__ sp) {
    const int row = blockIdx.x;
    const float* p = sp + row * WW;
    __shared__ float red[256];
    const int x = threadIdx.x;
    float v = p[x];
    red[x] = v * v;
    __syncthreads();
    for (int st = 128; st > 0; st >>= 1) {
        if (x < st) red[x] += red[x + st];
        __syncthreads();
    }
    float inv = 1.f / fmaxf(sqrtf(red[0]), 1e-12f);
    g_spn[row * WW + x] = v * inv;
}

// ---------------- K3b: proj conv 3->192 3x3 SAME -----------------------------
__global__ __launch_bounds__(256) void k3b_spmean(const float* __restrict__ wp) {
    const int y = blockIdx.x, oc = blockIdx.y;
    __shared__ float s[3][3][WW + 2];
    const int x = threadIdx.x;
#pragma unroll
    for (int ic = 0; ic < 3; ic++)
#pragma unroll
        for (int r = 0; r < 3; r++) {
            int yy = y - 1 + r;
            s[ic][r][x + 1] = (yy >= 0 && yy < HH) ? g_spn[ic * HW + yy * WW + x] : 0.f;
            if (x == 0) s[ic][r][0] = 0.f;
            if (x == 1) s[ic][r][WW + 1] = 0.f;
        }
    __syncthreads();
    float acc = 0.f;
    const float* w = wp + oc * 27;
#pragma unroll
    for (int ic = 0; ic < 3; ic++)
#pragma unroll
        for (int r = 0; r < 3; r++)
#pragma unroll
            for (int dc = 0; dc < 3; dc++)
                acc += __ldg(w + ic * 9 + r * 3 + dc) * s[ic][r][x + dc];
    g_spmean[oc * HW + y * WW + x] = acc;
}

// ---------------- K4: q row-l2norm (over W) * sp_mean -> qs (in place) -------
__global__ __launch_bounds__(256) void k4_qs() {
    const int y = blockIdx.x, c = blockIdx.y;
    float* q = g_buf2 + (size_t)c * HW + y * WW;
    __shared__ float red[256];
    const int x = threadIdx.x;
    float v = q[x];
    red[x] = v * v;
    __syncthreads();
    for (int st = 128; st > 0; st >>= 1) {
        if (x < st) red[x] += red[x + st];
        __syncthreads();
    }
    float inv = 1.f / fmaxf(sqrtf(red[0]), 1e-12f);
    q[x] = v * inv * g_spmean[c * HW + y * WW + x];
}

// ---------------- K5: Gram matrix S[c,d]=sum_n qs[c,n] k[d,n] + row sumsq ----
__global__ __launch_bounds__(256) void k5_gram() {
    const int chunk = blockIdx.x;
    const int hd = blockIdx.y;
    const int nbase = chunk * CHUNK;

    __shared__ float qs[128][33];
    __shared__ float ks[128][33];

    const int t = threadIdx.x;
    const int c0 = (t >> 4) * 2, d0 = (t & 15) * 2;
    const int lr = t >> 3;
    const int lc = (t & 7) * 4;

    float a00 = 0.f, a01 = 0.f, a10 = 0.f, a11 = 0.f, nacc = 0.f;

    const float* qbase = g_buf2 + (size_t)(hd * CC) * HW;
    const float* kbase = g_buf2 + (size_t)(DIM + hd * CC) * HW;

    for (int tile = 0; tile < CHUNK / 128; tile++) {
        const int n0 = nbase + tile * 128;
#pragma unroll
        for (int u = 0; u < 4; u++) {
            int col = lc + 32 * u;
            float4 qv = *(const float4*)(qbase + (size_t)lr * HW + n0 + col);
            qs[col + 0][lr] = qv.x; qs[col + 1][lr] = qv.y;
            qs[col + 2][lr] = qv.z; qs[col + 3][lr] = qv.w;
            float4 kv = *(const float4*)(kbase + (size_t)lr * HW + n0 + col);
            ks[col + 0][lr] = kv.x; ks[col + 1][lr] = kv.y;
            ks[col + 2][lr] = kv.z; ks[col + 3][lr] = kv.w;
        }
        __syncthreads();
#pragma unroll 4
        for (int nn = 0; nn < 128; nn++) {
            float q0 = qs[nn][c0], q1 = qs[nn][c0 + 1];
            float k0 = ks[nn][d0], k1 = ks[nn][d0 + 1];
            a00 += q0 * k0; a01 += q0 * k1;
            a10 += q1 * k0; a11 += q1 * k1;
        }
        if (t < 32) {
            for (int nn = 0; nn < 128; nn++) { float z = qs[nn][t]; nacc += z * z; }
        } else if (t < 64) {
            int d = t - 32;
            for (int nn = 0; nn < 128; nn++) { float z = ks[nn][d]; nacc += z * z; }
        }
        __syncthreads();
    }

    float* gp = g_gramp + ((size_t)chunk * HEADS + hd) * 1024;
    gp[c0 * 32 + d0] = a00;
    gp[c0 * 32 + d0 + 1] = a01;
    gp[(c0 + 1) * 32 + d0] = a10;
    gp[(c0 + 1) * 32 + d0 + 1] = a11;
    if (t < 32) g_nqp[(chunk * HEADS + hd) * 32 + t] = nacc;
    else if (t < 64) g_nkp[(chunk * HEADS + hd) * 32 + (t - 32)] = nacc;
}

// ---------------- K6: reduce partials, normalize, topk-soften, mix -> M ------
__global__ __launch_bounds__(1024) void k6_attn(const float* __restrict__ temp,
                                                const float* __restrict__ scales,
                                                const float* __restrict__ wmix) {
    const int hd = blockIdx.x;
    const int t = threadIdx.x;
    const int c = t >> 5, d = t & 31;

    float s = 0.f, nq = 0.f, nk = 0.f;
    for (int ch = 0; ch < NCHUNKS; ch++) {
        s += g_gramp[((size_t)ch * HEADS + hd) * 1024 + t];
        nq += g_nqp[(ch * HEADS + hd) * 32 + c];
        nk += g_nkp[(ch * HEADS + hd) * 32 + d];
    }
    float a = s * __ldg(temp + hd) /
              (fmaxf(sqrtf(nq), 1e-12f) * fmaxf(sqrtf(nk), 1e-12f));

    int cg = 0, ce = 0;
#pragma unroll
    for (int j = 0; j < 32; j++) {
        float aj = __shfl_sync(0xffffffffu, a, j);
        cg += (aj > a);
        ce += (aj == a);
    }

    float w0 = __ldg(wmix), w1 = __ldg(wmix + 1);
    float wm = fmaxf(w0, w1);
    float e0 = expf(w0 - wm), e1 = expf(w1 - wm);
    float w0s = e0 / (e0 + e1), w1s = e1 / (e0 + e1);
    float ssum = __ldg(scales) + __ldg(scales + 1) + __ldg(scales + 2) + __ldg(scales + 3);

    float acc = w0s * ssum * fmaxf(a, 0.f);

    const int kks[4] = {16, 21, 24, 25};
#pragma unroll
    for (int i = 0; i < 4; i++) {
        int kk = kks[i];
        unsigned mask = __ballot_sync(0xffffffffu, (cg < kk) && (kk <= cg + ce));
        float thr = __shfl_sync(0xffffffffu, a, __ffs(mask) - 1);
        float v = (a >= thr) ? a : a * 1e-6f;
        float mx = v;
#pragma unroll
        for (int off = 16; off > 0; off >>= 1) mx = fmaxf(mx, __shfl_xor_sync(0xffffffffu, mx, off));
        float e = expf(v - mx);
        float se = e;
#pragma unroll
        for (int off = 16; off > 0; off >>= 1) se += __shfl_xor_sync(0xffffffffu, se, off);
        acc += w1s * __ldg(scales + i) * (e / se);
    }
    g_M[hd * 1024 + c * 32 + d] = acc;
}

// ---------------- K6b: W2 = out_w (block) x M --------------------------------
__global__ __launch_bounds__(256) void k6b_w2(const float* __restrict__ ow) {
    const int idx = blockIdx.x * 256 + threadIdx.x;
    const int oc = idx / DIM;
    const int j = idx % DIM;
    const int hd = j >> 5, d = j & 31;
    const float* owp = ow + oc * DIM + hd * 32;
    const float* mp = g_M + hd * 1024 + d;
    float acc = 0.f;
#pragma unroll
    for (int cix = 0; cix < 32; cix++) acc += __ldg(owp + cix) * mp[cix * 32];
    g_W2[idx] = acc;
}

// -----------------------------------------------------------------------------
extern "C" void kernel_launch(void* const* d_in, const int* in_sizes, int n_in,
                              void* d_out, int out_size) {
    const float* x      = (const float*)d_in[0];
    const float* sp     = (const float*)d_in[1];
    const float* qkv_w  = (const float*)d_in[2];
    const float* dw_w   = (const float*)d_in[3];
    const float* proj_w = (const float*)d_in[4];
    const float* out_w  = (const float*)d_in[5];
    const float* temp   = (const float*)d_in[6];
    const float* scales = (const float*)d_in[7];
    const float* wmix   = (const float*)d_in[8];
    float* out = (float*)d_out;

    // batch-invariant superpixel path
    k3a_spnorm<<<768, 256>>>(sp);
    k3b_spmean<<<dim3(256, 192), 256>>>(proj_w);

    for (int b = 0; b < BB; b++) {
        const float* xb = x + (size_t)b * DIM * HW;
        float* ob = out + (size_t)b * DIM * HW;
        gemm_bf16<QDIM><<<dim3(512, 5), 256>>>(qkv_w, xb, nullptr);   // K1
        k2_dw<<<dim3(16, 576), 256>>>(dw_w);
        k4_qs<<<dim3(256, 192), 256>>>();
        k5_gram<<<dim3(NCHUNKS, HEADS), 256>>>();
        k6_attn<<<HEADS, 1024>>>(temp, scales, wmix);
        k6b_w2<<<144, 256>>>(out_w);
        gemm_bf16<DIM><<<dim3(512, 2), 256>>>(nullptr, nullptr, ob);  // K7
    }
}